// round 3
// baseline (speedup 1.0000x reference)
#include <cuda_runtime.h>
#include <cuda_bf16.h>
#include <math.h>

// ---------------- problem constants ----------------
#define BATCH 8192
#define LPOOL 10
#define NTAB  26
#define VROWS 200000
#define DIM   64
#define RDIM  415   // 64 + 351

// ---------------- scratch (device globals; no allocation) ----------------
__device__ float g_h1[BATCH * 512];          // bottom layer1 out
__device__ float g_h2[BATCH * 256];          // bottom layer2 out
__device__ float g_h3[BATCH * 64];           // bottom layer3 out
__device__ float g_pooled[NTAB * BATCH * DIM];
__device__ float g_R[BATCH * RDIM];
__device__ float g_z1[BATCH * 512];          // top layer1 out
__device__ float g_z2[BATCH * 256];          // top layer2 out

// ---------------- generic GEMM: C[M,N] = act(A[M,K] @ W[N,K]^T + bias[N]) ----------------
// M % 128 == 0, N % 64 == 0 guaranteed by the shapes here; K may be ragged.
#define BM 128
#define BN 64
#define BKK 16

__global__ __launch_bounds__(256) void gemm_bias_act(
    const float* __restrict__ A, const float* __restrict__ W,
    const float* __restrict__ bias, float* __restrict__ C,
    int M, int N, int K, int relu)
{
    __shared__ float As[BM][BKK + 1];
    __shared__ float Ws[BN][BKK + 1];

    const int tid = threadIdx.x;      // 0..255
    const int tx  = tid & 15;         // col group
    const int ty  = tid >> 4;         // row group
    const int m0  = blockIdx.y * BM;
    const int n0  = blockIdx.x * BN;

    float acc[8][4];
#pragma unroll
    for (int mi = 0; mi < 8; mi++)
#pragma unroll
        for (int ni = 0; ni < 4; ni++) acc[mi][ni] = 0.f;

    for (int k0 = 0; k0 < K; k0 += BKK) {
        // stage A tile (128x16) — 8 elems/thread, conflict-free
#pragma unroll
        for (int e = 0; e < 8; e++) {
            int el = tid + e * 256;
            int r = el >> 4, c = el & 15;
            int kk = k0 + c;
            As[r][c] = (kk < K) ? A[(size_t)(m0 + r) * K + kk] : 0.f;
        }
        // stage W tile (64x16) — 4 elems/thread
#pragma unroll
        for (int e = 0; e < 4; e++) {
            int el = tid + e * 256;
            int r = el >> 4, c = el & 15;
            int kk = k0 + c;
            Ws[r][c] = (kk < K) ? W[(size_t)(n0 + r) * K + kk] : 0.f;
        }
        __syncthreads();

#pragma unroll
        for (int k = 0; k < BKK; k++) {
            float a[8], w[4];
#pragma unroll
            for (int mi = 0; mi < 8; mi++) a[mi] = As[ty + 16 * mi][k];
#pragma unroll
            for (int ni = 0; ni < 4; ni++) w[ni] = Ws[tx + 16 * ni][k];
#pragma unroll
            for (int mi = 0; mi < 8; mi++)
#pragma unroll
                for (int ni = 0; ni < 4; ni++)
                    acc[mi][ni] = fmaf(a[mi], w[ni], acc[mi][ni]);
        }
        __syncthreads();
    }

#pragma unroll
    for (int ni = 0; ni < 4; ni++) {
        int n = n0 + tx + 16 * ni;
        float bv = bias[n];
#pragma unroll
        for (int mi = 0; mi < 8; mi++) {
            int m = m0 + ty + 16 * mi;
            float v = acc[mi][ni] + bv;
            if (relu) v = fmaxf(v, 0.f);
            C[(size_t)m * N + n] = v;
        }
    }
}

// ---------------- embedding bag sum-pool ----------------
// 256-thread block = 4 bags; within a bag 1 thread = 1 dim (coalesced 256B rows).
// NOTE: lS_i is int32 (JAX x64 disabled — jnp.int64 silently becomes int32).
__global__ __launch_bounds__(256) void embed_pool(
    const float* __restrict__ tables, const int* __restrict__ idx,
    float* __restrict__ pooled)
{
    const int bag = blockIdx.x * 4 + (threadIdx.x >> 6);   // t * BATCH + b
    const int d   = threadIdx.x & 63;
    const int t = bag >> 13;             // / 8192
    const int b = bag & (BATCH - 1);

    const int* bagIdx = idx + (size_t)t * (BATCH * LPOOL) + (size_t)b * LPOOL;
    const float* tab = tables + (size_t)t * VROWS * DIM;

    float s = 0.f;
#pragma unroll
    for (int l = 0; l < LPOOL; l++) {
        int r = __ldg(bagIdx + l);
        s += __ldg(tab + (size_t)r * DIM + d);
    }
    pooled[(size_t)bag * DIM + d] = s;
}

// ---------------- dot interaction ----------------
// one block per batch row: build T[27][64] in smem, emit R = [h (64) | Z lower-tri (351)]
__global__ __launch_bounds__(256) void interact(
    const float* __restrict__ h3, const float* __restrict__ pooled,
    float* __restrict__ R)
{
    const int b = blockIdx.x;
    __shared__ float T[27 * 64];

    for (int e = threadIdx.x; e < 27 * 64; e += 256) {
        int row = e >> 6, d = e & 63;
        T[e] = (row == 0) ? h3[(size_t)b * 64 + d]
                          : pooled[((size_t)(row - 1) * BATCH + b) * 64 + d];
    }
    __syncthreads();

    float* Rb = R + (size_t)b * RDIM;
    if (threadIdx.x < 64) Rb[threadIdx.x] = T[threadIdx.x];

    for (int p = threadIdx.x; p < 351; p += 256) {
        // invert p -> (i, j), i > j, row-major lower triangle (tril_indices order)
        int i = (int)((1.0f + sqrtf(8.0f * (float)p + 1.0f)) * 0.5f);
        while (i * (i - 1) / 2 > p) i--;
        while ((i + 1) * i / 2 <= p) i++;
        int j = p - i * (i - 1) / 2;

        const float4* Ti = (const float4*)(T + i * 64);
        const float4* Tj = (const float4*)(T + j * 64);
        float s = 0.f;
#pragma unroll
        for (int k = 0; k < 16; k++) {
            float4 a = Ti[k], c = Tj[k];
            s += a.x * c.x + a.y * c.y + a.z * c.z + a.w * c.w;
        }
        Rb[64 + p] = s;
    }
}

// ---------------- final layer: out = sigmoid(z2 @ w3^T + b3), N=1 ----------------
__global__ __launch_bounds__(256) void top3_sigmoid(
    const float* __restrict__ z2, const float* __restrict__ w,
    const float* __restrict__ bias, float* __restrict__ out)
{
    const int warp = (blockIdx.x * blockDim.x + threadIdx.x) >> 5;
    const int lane = threadIdx.x & 31;
    if (warp >= BATCH) return;

    const float* zr = z2 + (size_t)warp * 256;
    float s = 0.f;
#pragma unroll
    for (int k = 0; k < 8; k++)
        s += zr[lane + 32 * k] * w[lane + 32 * k];
#pragma unroll
    for (int off = 16; off; off >>= 1)
        s += __shfl_down_sync(0xffffffffu, s, off);
    if (lane == 0)
        out[warp] = 1.f / (1.f + expf(-(s + bias[0])));
}

// ---------------- launch ----------------
extern "C" void kernel_launch(void* const* d_in, const int* in_sizes, int n_in,
                              void* d_out, int out_size)
{
    const float* x    = (const float*)d_in[0];
    const int*   lS_i = (const int*)d_in[1];   // int32: JAX default x64-disabled
    // d_in[2] = lS_o: fixed arange(B)*L by construction; unused.
    const float* emb = (const float*)d_in[3];
    const float* bW1 = (const float*)d_in[4],  *bb1 = (const float*)d_in[5];
    const float* bW2 = (const float*)d_in[6],  *bb2 = (const float*)d_in[7];
    const float* bW3 = (const float*)d_in[8],  *bb3 = (const float*)d_in[9];
    const float* tW1 = (const float*)d_in[10], *tb1 = (const float*)d_in[11];
    const float* tW2 = (const float*)d_in[12], *tb2 = (const float*)d_in[13];
    const float* tW3 = (const float*)d_in[14], *tb3 = (const float*)d_in[15];
    float* out = (float*)d_out;

    float *h1, *h2, *h3, *pooled, *R, *z1, *z2;
    cudaGetSymbolAddress((void**)&h1, g_h1);
    cudaGetSymbolAddress((void**)&h2, g_h2);
    cudaGetSymbolAddress((void**)&h3, g_h3);
    cudaGetSymbolAddress((void**)&pooled, g_pooled);
    cudaGetSymbolAddress((void**)&R, g_R);
    cudaGetSymbolAddress((void**)&z1, g_z1);
    cudaGetSymbolAddress((void**)&z2, g_z2);

    // embedding pool first (independent of MLP chain)
    embed_pool<<<NTAB * BATCH / 4, 256>>>(emb, lS_i, pooled);

    // bottom MLP
    gemm_bias_act<<<dim3(512 / BN, BATCH / BM), 256>>>(x,  bW1, bb1, h1, BATCH, 512, 13,  1);
    gemm_bias_act<<<dim3(256 / BN, BATCH / BM), 256>>>(h1, bW2, bb2, h2, BATCH, 256, 512, 1);
    gemm_bias_act<<<dim3(64  / BN, BATCH / BM), 256>>>(h2, bW3, bb3, h3, BATCH, 64,  256, 1);

    // interaction
    interact<<<BATCH, 256>>>(h3, pooled, R);

    // top MLP
    gemm_bias_act<<<dim3(512 / BN, BATCH / BM), 256>>>(R,  tW1, tb1, z1, BATCH, 512, RDIM, 1);
    gemm_bias_act<<<dim3(256 / BN, BATCH / BM), 256>>>(z1, tW2, tb2, z2, BATCH, 256, 512,  1);
    top3_sigmoid<<<BATCH / 8, 256>>>(z2, tW3, tb3, out);
}

// round 5
// speedup vs baseline: 1.4298x; 1.4298x over previous
#include <cuda_runtime.h>
#include <cuda_bf16.h>
#include <math.h>

// ---------------- problem constants ----------------
#define BATCH 8192
#define LPOOL 10
#define NTAB  26
#define VROWS 200000
#define DIM   64
#define RDIM  415   // 64 + 351
#define RPAD  416   // padded stride (%32 == 0, 16B aligned)

// ---------------- scratch (device globals; no allocation) ----------------
__device__ float g_h1[BATCH * 512];
__device__ float g_h2[BATCH * 256];
__device__ float g_h3[BATCH * 64];
__device__ float g_pooled[NTAB * BATCH * DIM];
__device__ float g_R[BATCH * RPAD];
__device__ float g_z1[BATCH * 512];
__device__ float g_z2[BATCH * 256];

// ============================================================
// TF32 tensor-core GEMM: C[M,N] = act(A[M,K] @ W[N,K]^T + bias)
// BM=128, BN=64, BK=32; 256 threads = 8 warps (4 m x 2 n),
// warp tile 32x32 = 2x4 m16n8k8 mma tiles.
// Requirements: M%128==0, N%64==0, Kt%32==0, A has lda stride with
// zero-padding up to Kt; W guarded to Kreal columns.
// ============================================================
__device__ __forceinline__ unsigned f2tf32(float x) {
    unsigned r;
    asm("cvt.rna.tf32.f32 %0, %1;" : "=r"(r) : "f"(x));
    return r;
}

__device__ __forceinline__ void mma_tf32(float* c, const unsigned* a, const unsigned* b) {
    asm volatile(
        "mma.sync.aligned.m16n8k8.row.col.f32.tf32.tf32.f32 "
        "{%0,%1,%2,%3}, {%4,%5,%6,%7}, {%8,%9}, {%0,%1,%2,%3};"
        : "+f"(c[0]), "+f"(c[1]), "+f"(c[2]), "+f"(c[3])
        : "r"(a[0]), "r"(a[1]), "r"(a[2]), "r"(a[3]), "r"(b[0]), "r"(b[1]));
}

#define GBM 128
#define GBN 64
#define GBK 32
#define SKP (GBK + 4)

__global__ __launch_bounds__(256) void gemm_tf32(
    const float* __restrict__ A, int lda,
    const float* __restrict__ W, int ldw,
    const float* __restrict__ bias, float* __restrict__ C,
    int M, int N, int Kt, int Kreal, int relu)
{
    __shared__ unsigned As[GBM][SKP];
    __shared__ unsigned Ws[GBN][SKP];

    const int tid  = threadIdx.x;
    const int lane = tid & 31;
    const int wid  = tid >> 5;
    const int wm   = wid & 3;      // warp row 0..3 (32 rows each)
    const int wn   = wid >> 2;     // warp col 0..1 (32 cols each)
    const int m0   = blockIdx.y * GBM;
    const int n0   = blockIdx.x * GBN;

    const int qr = lane >> 2;      // 0..7  (row within m16/n8 groups)
    const int qc = lane & 3;       // 0..3  (k within group)

    float acc[2][4][4];
#pragma unroll
    for (int mt = 0; mt < 2; mt++)
#pragma unroll
        for (int nt = 0; nt < 4; nt++)
#pragma unroll
            for (int e = 0; e < 4; e++) acc[mt][nt][e] = 0.f;

    for (int k0 = 0; k0 < Kt; k0 += GBK) {
        // stage A tile (128x32): 16 scalars/thread, coalesced
#pragma unroll
        for (int i = 0; i < 16; i++) {
            int idx = tid + i * 256;
            int r = idx >> 5, k = idx & 31;
            As[r][k] = f2tf32(A[(size_t)(m0 + r) * lda + k0 + k]);
        }
        // stage W tile (64x32): 8 scalars/thread, guard ragged Kreal
#pragma unroll
        for (int i = 0; i < 8; i++) {
            int idx = tid + i * 256;
            int r = idx >> 5, k = idx & 31;
            int kk = k0 + k;
            float v = (kk < Kreal) ? W[(size_t)(n0 + r) * ldw + kk] : 0.f;
            Ws[r][k] = f2tf32(v);
        }
        __syncthreads();

#pragma unroll
        for (int ks = 0; ks < 4; ks++) {
            unsigned a[2][4], b[4][2];
            const int kb = ks * 8;
#pragma unroll
            for (int mt = 0; mt < 2; mt++) {
                int r = wm * 32 + mt * 16 + qr;
                a[mt][0] = As[r][kb + qc];
                a[mt][1] = As[r + 8][kb + qc];
                a[mt][2] = As[r][kb + qc + 4];
                a[mt][3] = As[r + 8][kb + qc + 4];
            }
#pragma unroll
            for (int nt = 0; nt < 4; nt++) {
                int n = wn * 32 + nt * 8 + qr;
                b[nt][0] = Ws[n][kb + qc];
                b[nt][1] = Ws[n][kb + qc + 4];
            }
#pragma unroll
            for (int mt = 0; mt < 2; mt++)
#pragma unroll
                for (int nt = 0; nt < 4; nt++)
                    mma_tf32(acc[mt][nt], a[mt], b[nt]);
        }
        __syncthreads();
    }

    // epilogue: bias + relu, float2 stores
#pragma unroll
    for (int mt = 0; mt < 2; mt++) {
#pragma unroll
        for (int nt = 0; nt < 4; nt++) {
            int row = m0 + wm * 32 + mt * 16 + qr;
            int col = n0 + wn * 32 + nt * 8 + qc * 2;
            float bv0 = bias[col], bv1 = bias[col + 1];
            float v0 = acc[mt][nt][0] + bv0;
            float v1 = acc[mt][nt][1] + bv1;
            float v2 = acc[mt][nt][2] + bv0;
            float v3 = acc[mt][nt][3] + bv1;
            if (relu) {
                v0 = fmaxf(v0, 0.f); v1 = fmaxf(v1, 0.f);
                v2 = fmaxf(v2, 0.f); v3 = fmaxf(v3, 0.f);
            }
            *(float2*)&C[(size_t)row * N + col]       = make_float2(v0, v1);
            *(float2*)&C[(size_t)(row + 8) * N + col] = make_float2(v2, v3);
        }
    }
}

// ---------------- SIMT GEMM (kept for bot1, K=13) ----------------
#define BM 128
#define BN 64
#define BKK 16

__global__ __launch_bounds__(256) void gemm_bias_act(
    const float* __restrict__ A, const float* __restrict__ W,
    const float* __restrict__ bias, float* __restrict__ C,
    int M, int N, int K, int relu)
{
    __shared__ float As[BM][BKK + 1];
    __shared__ float Ws[BN][BKK + 1];

    const int tid = threadIdx.x;
    const int tx  = tid & 15;
    const int ty  = tid >> 4;
    const int m0  = blockIdx.y * BM;
    const int n0  = blockIdx.x * BN;

    float acc[8][4];
#pragma unroll
    for (int mi = 0; mi < 8; mi++)
#pragma unroll
        for (int ni = 0; ni < 4; ni++) acc[mi][ni] = 0.f;

    for (int k0 = 0; k0 < K; k0 += BKK) {
#pragma unroll
        for (int e = 0; e < 8; e++) {
            int el = tid + e * 256;
            int r = el >> 4, c = el & 15;
            int kk = k0 + c;
            As[r][c] = (kk < K) ? A[(size_t)(m0 + r) * K + kk] : 0.f;
        }
#pragma unroll
        for (int e = 0; e < 4; e++) {
            int el = tid + e * 256;
            int r = el >> 4, c = el & 15;
            int kk = k0 + c;
            Ws[r][c] = (kk < K) ? W[(size_t)(n0 + r) * K + kk] : 0.f;
        }
        __syncthreads();

#pragma unroll
        for (int k = 0; k < BKK; k++) {
            float a[8], w[4];
#pragma unroll
            for (int mi = 0; mi < 8; mi++) a[mi] = As[ty + 16 * mi][k];
#pragma unroll
            for (int ni = 0; ni < 4; ni++) w[ni] = Ws[tx + 16 * ni][k];
#pragma unroll
            for (int mi = 0; mi < 8; mi++)
#pragma unroll
                for (int ni = 0; ni < 4; ni++)
                    acc[mi][ni] = fmaf(a[mi], w[ni], acc[mi][ni]);
        }
        __syncthreads();
    }

#pragma unroll
    for (int ni = 0; ni < 4; ni++) {
        int n = n0 + tx + 16 * ni;
        float bv = bias[n];
#pragma unroll
        for (int mi = 0; mi < 8; mi++) {
            int m = m0 + ty + 16 * mi;
            float v = acc[mi][ni] + bv;
            if (relu) v = fmaxf(v, 0.f);
            C[(size_t)m * N + n] = v;
        }
    }
}

// ---------------- embedding bag sum-pool ----------------
__global__ __launch_bounds__(256) void embed_pool(
    const float* __restrict__ tables, const int* __restrict__ idx,
    float* __restrict__ pooled)
{
    const int bag = blockIdx.x * 4 + (threadIdx.x >> 6);   // t * BATCH + b
    const int d   = threadIdx.x & 63;
    const int t = bag >> 13;
    const int b = bag & (BATCH - 1);

    const int* bagIdx = idx + (size_t)t * (BATCH * LPOOL) + (size_t)b * LPOOL;
    const float* tab = tables + (size_t)t * VROWS * DIM;

    float s = 0.f;
#pragma unroll
    for (int l = 0; l < LPOOL; l++) {
        int r = __ldg(bagIdx + l);
        s += __ldg(tab + (size_t)r * DIM + d);
    }
    pooled[(size_t)bag * DIM + d] = s;
}

// ---------------- dot interaction (writes R with RPAD stride) ----------------
__global__ __launch_bounds__(256) void interact(
    const float* __restrict__ h3, const float* __restrict__ pooled,
    float* __restrict__ R)
{
    const int b = blockIdx.x;
    __shared__ float T[27 * 64];

    for (int e = threadIdx.x; e < 27 * 64; e += 256) {
        int row = e >> 6, d = e & 63;
        T[e] = (row == 0) ? h3[(size_t)b * 64 + d]
                          : pooled[((size_t)(row - 1) * BATCH + b) * 64 + d];
    }
    __syncthreads();

    float* Rb = R + (size_t)b * RPAD;
    if (threadIdx.x < 64) Rb[threadIdx.x] = T[threadIdx.x];
    if (threadIdx.x == 64) Rb[RDIM] = 0.f;   // zero pad column (K=416)

    for (int p = threadIdx.x; p < 351; p += 256) {
        int i = (int)((1.0f + sqrtf(8.0f * (float)p + 1.0f)) * 0.5f);
        while (i * (i - 1) / 2 > p) i--;
        while ((i + 1) * i / 2 <= p) i++;
        int j = p - i * (i - 1) / 2;

        const float4* Ti = (const float4*)(T + i * 64);
        const float4* Tj = (const float4*)(T + j * 64);
        float s = 0.f;
#pragma unroll
        for (int k = 0; k < 16; k++) {
            float4 a = Ti[k], c = Tj[k];
            s += a.x * c.x + a.y * c.y + a.z * c.z + a.w * c.w;
        }
        Rb[64 + p] = s;
    }
}

// ---------------- final layer: sigmoid(z2 @ w3^T + b3) ----------------
__global__ __launch_bounds__(256) void top3_sigmoid(
    const float* __restrict__ z2, const float* __restrict__ w,
    const float* __restrict__ bias, float* __restrict__ out)
{
    const int warp = (blockIdx.x * blockDim.x + threadIdx.x) >> 5;
    const int lane = threadIdx.x & 31;
    if (warp >= BATCH) return;

    const float* zr = z2 + (size_t)warp * 256;
    float s = 0.f;
#pragma unroll
    for (int k = 0; k < 8; k++)
        s += zr[lane + 32 * k] * w[lane + 32 * k];
#pragma unroll
    for (int off = 16; off; off >>= 1)
        s += __shfl_down_sync(0xffffffffu, s, off);
    if (lane == 0)
        out[warp] = 1.f / (1.f + expf(-(s + bias[0])));
}

// ---------------- launch ----------------
extern "C" void kernel_launch(void* const* d_in, const int* in_sizes, int n_in,
                              void* d_out, int out_size)
{
    const float* x    = (const float*)d_in[0];
    const int*   lS_i = (const int*)d_in[1];   // int32 (JAX x64 disabled)
    const float* emb = (const float*)d_in[3];
    const float* bW1 = (const float*)d_in[4],  *bb1 = (const float*)d_in[5];
    const float* bW2 = (const float*)d_in[6],  *bb2 = (const float*)d_in[7];
    const float* bW3 = (const float*)d_in[8],  *bb3 = (const float*)d_in[9];
    const float* tW1 = (const float*)d_in[10], *tb1 = (const float*)d_in[11];
    const float* tW2 = (const float*)d_in[12], *tb2 = (const float*)d_in[13];
    const float* tW3 = (const float*)d_in[14], *tb3 = (const float*)d_in[15];
    float* out = (float*)d_out;

    float *h1, *h2, *h3, *pooled, *R, *z1, *z2;
    cudaGetSymbolAddress((void**)&h1, g_h1);
    cudaGetSymbolAddress((void**)&h2, g_h2);
    cudaGetSymbolAddress((void**)&h3, g_h3);
    cudaGetSymbolAddress((void**)&pooled, g_pooled);
    cudaGetSymbolAddress((void**)&R, g_R);
    cudaGetSymbolAddress((void**)&z1, g_z1);
    cudaGetSymbolAddress((void**)&z2, g_z2);

    // embedding pool (independent of MLP chain)
    embed_pool<<<NTAB * BATCH / 4, 256>>>(emb, lS_i, pooled);

    // bottom MLP
    gemm_bias_act<<<dim3(512 / BN, BATCH / BM), 256>>>(x, bW1, bb1, h1, BATCH, 512, 13, 1);
    gemm_tf32<<<dim3(256 / GBN, BATCH / GBM), 256>>>(h1, 512, bW2, 512, bb2, h2,
                                                     BATCH, 256, 512, 512, 1);
    gemm_tf32<<<dim3(64 / GBN, BATCH / GBM), 256>>>(h2, 256, bW3, 256, bb3, h3,
                                                    BATCH, 64, 256, 256, 1);

    // interaction (R stride = RPAD, pad col zeroed)
    interact<<<BATCH, 256>>>(h3, pooled, R);

    // top MLP
    gemm_tf32<<<dim3(512 / GBN, BATCH / GBM), 256>>>(R, RPAD, tW1, RDIM, tb1, z1,
                                                     BATCH, 512, RPAD, RDIM, 1);
    gemm_tf32<<<dim3(256 / GBN, BATCH / GBM), 256>>>(z1, 512, tW2, 512, tb2, z2,
                                                     BATCH, 256, 512, 512, 1);
    top3_sigmoid<<<BATCH / 8, 256>>>(z2, tW3, tb3, out);
}